// round 14
// baseline (speedup 1.0000x reference)
#include <cuda_runtime.h>
#include <cuda_bf16.h>
#include <math.h>
#include <stdint.h>

// ---------------- problem constants ----------------
#define Bb   4
#define Ll   2048
#define Dd   1024
#define Ee   8
#define FFf  4096
#define F_TOT (Bb*Ll)            // 8192
#define CAP   2560               // int(8192*2/8*1.25)

#if defined(__CUDA_ARCH_FEAT_SM103_ALL) || defined(__CUDA_ARCH_SPECIFIC__)
#define HAS_TCGEN05 1
#else
#define HAS_TCGEN05 0
#endif

// ---------------- scratch ----------------
__device__ int   g_topi [F_TOT * 2];
__device__ float g_gate [F_TOT * 2];
__device__ int   g_pos  [F_TOT * 2];
__device__ int   g_disp [Ee * CAP];
__device__ int   g_count[Ee];
__device__ __nv_bfloat16 g_xin_h[(size_t)Ee * CAP * Dd];
__device__ __nv_bfloat16 g_xin_l[(size_t)Ee * CAP * Dd];
__device__ __nv_bfloat16 g_w1t_h[(size_t)Ee * FFf * Dd];
__device__ __nv_bfloat16 g_w1t_l[(size_t)Ee * FFf * Dd];
__device__ __nv_bfloat16 g_w2t_h[(size_t)Ee * Dd * FFf];
__device__ __nv_bfloat16 g_w2t_l[(size_t)Ee * Dd * FFf];
__device__ __nv_bfloat16 g_h_h  [(size_t)Ee * CAP * FFf];
__device__ __nv_bfloat16 g_h_l  [(size_t)Ee * CAP * FFf];
__device__ float         g_out2 [(size_t)Ee * CAP * Dd];

// ---------------- helpers ----------------
__device__ __forceinline__ uint32_t smem_u32(const void* p) {
    uint32_t a;
    asm("{ .reg .u64 t; cvta.to.shared.u64 t, %1; cvt.u32.u64 %0, t; }" : "=r"(a) : "l"(p));
    return a;
}
#define CP_COMMIT() asm volatile("cp.async.commit_group;" ::: "memory")
#define SW64SW(o) ((o) ^ ((((uint32_t)(o)) >> 3) & 0x30))

#define MBAR_WAIT(mbar, par) do {                                             \
    asm volatile("{\n\t.reg .pred P1;\n\t"                                    \
        "WL_%=:\n\t"                                                          \
        "mbarrier.try_wait.parity.acquire.cta.shared::cta.b64 P1, [%0], %1, 0x989680;\n\t" \
        "@P1 bra.uni WD_%=;\n\tbra.uni WL_%=;\n\tWD_%=:\n\t}"                \
        :: "r"(mbar), "r"(par) : "memory");                                   \
} while (0)

// ---------------- 1. gating ----------------
__global__ void gating_kernel(const float* __restrict__ x,
                              const float* __restrict__ noise,
                              const float* __restrict__ Wg, const float* __restrict__ bg,
                              const float* __restrict__ Wn, const float* __restrict__ bn)
{
    int warp = (blockIdx.x * blockDim.x + threadIdx.x) >> 5;
    int lane = threadIdx.x & 31;
    if (warp >= F_TOT) return;
    const float* xr = x + (size_t)warp * Dd;
    float ag[Ee], an[Ee];
#pragma unroll
    for (int e = 0; e < Ee; e++) { ag[e] = 0.f; an[e] = 0.f; }
    for (int d = lane; d < Dd; d += 32) {
        float xv = xr[d];
#pragma unroll
        for (int e = 0; e < Ee; e++) {
            ag[e] = fmaf(xv, Wg[d * Ee + e], ag[e]);
            an[e] = fmaf(xv, Wn[d * Ee + e], an[e]);
        }
    }
#pragma unroll
    for (int off = 16; off > 0; off >>= 1)
#pragma unroll
        for (int e = 0; e < Ee; e++) {
            ag[e] += __shfl_down_sync(0xffffffffu, ag[e], off);
            an[e] += __shfl_down_sync(0xffffffffu, an[e], off);
        }
    if (lane == 0) {
        float noisy[Ee];
#pragma unroll
        for (int e = 0; e < Ee; e++) {
            float l  = ag[e] + bg[e];
            float nl = an[e] + bn[e];
            float sp = fmaxf(nl, 0.f) + log1pf(expf(-fabsf(nl)));
            noisy[e] = l + noise[(size_t)warp * Ee + e] * sp;
        }
        int i0 = 0;
#pragma unroll
        for (int e = 1; e < Ee; e++) if (noisy[e] > noisy[i0]) i0 = e;
        int i1 = -1;
#pragma unroll
        for (int e = 0; e < Ee; e++) {
            if (e == i0) continue;
            if (i1 < 0 || noisy[e] > noisy[i1]) i1 = e;
        }
        float z = expf(noisy[i1] - noisy[i0]);
        float g0 = 1.f / (1.f + z);
        g_topi[warp * 2 + 0] = i0;
        g_topi[warp * 2 + 1] = i1;
        g_gate[warp * 2 + 0] = g0;
        g_gate[warp * 2 + 1] = z * g0;
    }
}

// ---------------- 2. per-expert token-order scan ----------------
__global__ void scan_kernel()
{
    const int e = blockIdx.x;
    const int tid = threadIdx.x;
    __shared__ int sdata[256];
    __shared__ int sbase;
    if (tid == 0) sbase = 0;
    __syncthreads();
    for (int start = 0; start < F_TOT; start += 256) {
        int t = start + tid;
        int i0 = g_topi[t * 2 + 0];
        int i1 = g_topi[t * 2 + 1];
        int m = (i0 == e || i1 == e) ? 1 : 0;
        sdata[tid] = m;
        __syncthreads();
#pragma unroll
        for (int off = 1; off < 256; off <<= 1) {
            int v = (tid >= off) ? sdata[tid - off] : 0;
            __syncthreads();
            sdata[tid] += v;
            __syncthreads();
        }
        int p = sbase + sdata[tid] - 1;
        if (m) {
            int k = (i0 == e) ? 0 : 1;
            if (p < CAP) { g_disp[e * CAP + p] = t; g_pos[t * 2 + k] = p; }
            else         { g_pos[t * 2 + k] = -1; }
        }
        __syncthreads();
        if (tid == 0) sbase += sdata[255];
        __syncthreads();
    }
    if (tid == 0) g_count[e] = min(sbase, CAP);
}

// ---------------- 3. fused prep ----------------
__global__ void fused_prep_kernel(const float* __restrict__ W1, const float* __restrict__ W2,
                                  const float* __restrict__ x)
{
    int id = blockIdx.x;
    if (id < 65536) {
        __shared__ float tile[32][33];
        const float* W; __nv_bfloat16 *Th, *Tl;
        int R, C, bx, by, e;
        if (id < 32768) {
            W = W1; Th = g_w1t_h; Tl = g_w1t_l; R = Dd; C = FFf;
            bx = id & 127; by = (id >> 7) & 31; e = id >> 12;
        } else {
            id -= 32768;
            W = W2; Th = g_w2t_h; Tl = g_w2t_l; R = FFf; C = Dd;
            bx = id & 31; by = (id >> 5) & 127; e = id >> 12;
        }
        int tx = threadIdx.x & 31, ty = threadIdx.x >> 5;
        const float* We = W + (size_t)e * R * C;
        int c = bx * 32 + tx;
#pragma unroll
        for (int j = 0; j < 4; j++) {
            int r = by * 32 + ty + j * 8;
            tile[ty + j * 8][tx] = We[(size_t)r * C + c];
        }
        __syncthreads();
        int r2 = by * 32 + tx;
        size_t ebase = (size_t)e * C * R;
#pragma unroll
        for (int j = 0; j < 4; j++) {
            int c2 = bx * 32 + ty + j * 8;
            float v = tile[tx][ty + j * 8];
            __nv_bfloat16 h = __float2bfloat16(v);
            __nv_bfloat16 l = __float2bfloat16(v - __bfloat162float(h));
            Th[ebase + (size_t)c2 * R + r2] = h;
            Tl[ebase + (size_t)c2 * R + r2] = l;
        }
    } else {
        int gid = id - 65536;
        int e = gid / CAP;
        int c = gid % CAP;
        size_t base = ((size_t)e * CAP + c) * Dd + threadIdx.x * 4;
        if (c < g_count[e]) {
            int t = g_disp[e * CAP + c];
            float4 v = ((const float4*)(x + (size_t)t * Dd))[threadIdx.x];
            float vv[4] = {v.x, v.y, v.z, v.w};
#pragma unroll
            for (int q = 0; q < 4; q += 2) {
                __nv_bfloat16 h0 = __float2bfloat16(vv[q]);
                __nv_bfloat16 h1 = __float2bfloat16(vv[q + 1]);
                __nv_bfloat16 l0 = __float2bfloat16(vv[q] - __bfloat162float(h0));
                __nv_bfloat16 l1 = __float2bfloat16(vv[q + 1] - __bfloat162float(h1));
                *(__nv_bfloat162*)(g_xin_h + base + q) = __halves2bfloat162(h0, h1);
                *(__nv_bfloat162*)(g_xin_l + base + q) = __halves2bfloat162(l0, l1);
            }
        } else {
            __nv_bfloat162 z = __halves2bfloat162(__float2bfloat16(0.f), __float2bfloat16(0.f));
#pragma unroll
            for (int q = 0; q < 4; q += 2) {
                *(__nv_bfloat162*)(g_xin_h + base + q) = z;
                *(__nv_bfloat162*)(g_xin_l + base + q) = z;
            }
        }
    }
}

// ---------------- 4. persistent GEMM, 2 CTAs/SM, tile 128x128, BK=32, 3 stages x 32KB ----
// stage: Ah(8K)@0 Al(8K)@8192 Bh(8K)@16384 Bl(8K)@24576, SW64 rows.
// warps 0-7 consumers, warp 8 MMA, warps 9-11 loaders (96 threads).
// header: [0] tmem; sd[3]@16..32 (cnt1); td[2]@48/56 (cnt1); tf[2]@64/72 (cnt256);
//         dr[3]@80..96 (cnt96).
#define PSTG 32768u

__global__ void __launch_bounds__(384, 2)
moe_gemm_persist(const __nv_bfloat16* __restrict__ Ah, const __nv_bfloat16* __restrict__ Al,
                 const __nv_bfloat16* __restrict__ Bh, const __nv_bfloat16* __restrict__ Bl,
                 const float* __restrict__ bias,
                 __nv_bfloat16* __restrict__ outH, __nv_bfloat16* __restrict__ outL,
                 float* __restrict__ outF,
                 int K, int Ntot, int mode)
{
#if HAS_TCGEN05
    extern __shared__ __align__(1024) char smem[];
    const int tid = threadIdx.x, wid = tid >> 5, lid = tid & 31;
    const int gx = Ntot >> 7;            // 128-wide N tiles
    const int gy = CAP >> 7;             // 20
    const int TT = gx * gy * Ee;
    const int S = K >> 5;                // BK=32
    uint32_t sb = smem_u32(smem);
    uint32_t sd[3] = {sb + 16, sb + 24, sb + 32};
    uint32_t td[2] = {sb + 48, sb + 56};
    uint32_t tf[2] = {sb + 64, sb + 72};
    uint32_t dr[3] = {sb + 80, sb + 88, sb + 96};
    if (tid == 0) {
#pragma unroll
        for (int b = 0; b < 3; b++) {
            asm volatile("mbarrier.init.shared.b64 [%0], 1;"  :: "r"(sd[b]) : "memory");
            asm volatile("mbarrier.init.shared.b64 [%0], 96;" :: "r"(dr[b]) : "memory");
        }
#pragma unroll
        for (int b = 0; b < 2; b++) {
            asm volatile("mbarrier.init.shared.b64 [%0], 1;"   :: "r"(td[b]) : "memory");
            asm volatile("mbarrier.init.shared.b64 [%0], 256;" :: "r"(tf[b]) : "memory");
        }
    }
    if (wid == 8)
        asm volatile("tcgen05.alloc.cta_group::1.sync.aligned.shared::cta.b32 [%0], 256;"
                     :: "r"(sb) : "memory");
    __syncthreads();
    uint32_t tmem;
    asm volatile("ld.shared.b32 %0, [%1];" : "=r"(tmem) : "r"(sb));

    if (wid == 8) {
        // ======== MMA warp (lane 0 issues) ========
        if (lid == 0) {
            const uint32_t IDESC = (8u << 24) | (16u << 17) | (1u << 10) | (1u << 7) | (1u << 4);
            const uint64_t DB = ((uint64_t)4 << 61) | ((uint64_t)1 << 46) |
                                ((uint64_t)32 << 32) | ((uint64_t)1 << 16);
            int drPh[3] = {0, 0, 0}, tfPh[2] = {0, 0}, tfFirst[2] = {1, 1};
            long q = 0;
            int bq = 0;                  // q % 3
            int halfUse = 0;
            for (int T = blockIdx.x; T < TT; T += gridDim.x) {
                int e = T / (gx * gy), r = T % (gx * gy), y = r / gx;
                if (y * 128 >= g_count[e]) continue;
                int half = halfUse & 1; halfUse++;
                uint32_t dacc = tmem + (uint32_t)half * 128;
                for (int s = 0; s < S; s++) {
                    int b = bq;
                    MBAR_WAIT(dr[b], drPh[b]); drPh[b] ^= 1;
                    if (s == 0) {
                        if (!tfFirst[half]) {
                            MBAR_WAIT(tf[half], tfPh[half]); tfPh[half] ^= 1;
                            asm volatile("tcgen05.fence::after_thread_sync;" ::: "memory");
                        } else tfFirst[half] = 0;
                    }
                    uint32_t stoff = sb + 1024 + (uint32_t)b * PSTG;
                    uint64_t dAh = DB | ((stoff >> 4) & 0x3FFF);
                    uint64_t dAl = DB | (((stoff + 8192u) >> 4) & 0x3FFF);
                    uint64_t dBh = DB | (((stoff + 16384u) >> 4) & 0x3FFF);
                    uint64_t dBl = DB | (((stoff + 24576u) >> 4) & 0x3FFF);
#pragma unroll
                    for (int kc = 0; kc < 2; kc++) {
                        uint32_t en = (s | kc) != 0;
                        asm volatile("{ .reg .pred p; setp.ne.u32 p, %4, 0;\n\t"
                            "tcgen05.mma.cta_group::1.kind::f16 [%0], %1, %2, %3, {%5,%5,%5,%5}, p; }"
                            :: "r"(dacc), "l"(dAh + kc * 2), "l"(dBh + kc * 2), "r"(IDESC),
                               "r"(en), "r"(0u) : "memory");
                    }
#pragma unroll
                    for (int kc = 0; kc < 2; kc++)
                        asm volatile("{ .reg .pred p; setp.ne.u32 p, 1, 0;\n\t"
                            "tcgen05.mma.cta_group::1.kind::f16 [%0], %1, %2, %3, {%4,%4,%4,%4}, p; }"
                            :: "r"(dacc), "l"(dAh + kc * 2), "l"(dBl + kc * 2), "r"(IDESC), "r"(0u) : "memory");
#pragma unroll
                    for (int kc = 0; kc < 2; kc++)
                        asm volatile("{ .reg .pred p; setp.ne.u32 p, 1, 0;\n\t"
                            "tcgen05.mma.cta_group::1.kind::f16 [%0], %1, %2, %3, {%4,%4,%4,%4}, p; }"
                            :: "r"(dacc), "l"(dAl + kc * 2), "l"(dBh + kc * 2), "r"(IDESC), "r"(0u) : "memory");
                    asm volatile("tcgen05.commit.cta_group::1.mbarrier::arrive::one.shared::cluster.b64 [%0];"
                                 :: "r"(sd[b]) : "memory");
                    if (s == S - 1)
                        asm volatile("tcgen05.commit.cta_group::1.mbarrier::arrive::one.shared::cluster.b64 [%0];"
                                     :: "r"(td[half]) : "memory");
                    q++;
                    if (++bq == 3) bq = 0;
                }
            }
        }
    } else if (wid >= 9) {
        // ======== LOADER warps (9-11, 96 threads) ========
        const int p = tid - 288;          // 0..95
        int emT = -1, emS = 0;
        long emIdx = 0;
        int emB = 0;                      // emIdx % 3
        for (int T = blockIdx.x; T < TT; T += gridDim.x) {
            int e = T / (gx * gy), r = T % (gx * gy), y = r / gx;
            if (y * 128 < g_count[e]) { emT = T; break; }
        }
        auto emitOne = [&]() {
            int e = emT / (gx * gy), r = emT % (gx * gy), y = r / gx, x2 = r - y * gx;
            int m0 = y * 128, n0 = x2 * 128, k0 = emS * 32;
            const __nv_bfloat16* teAh = Ah + (size_t)e * CAP * K;
            const __nv_bfloat16* teAl = Al + (size_t)e * CAP * K;
            const __nv_bfloat16* teBh = Bh + (size_t)e * Ntot * K;
            const __nv_bfloat16* teBl = Bl + (size_t)e * Ntot * K;
            uint32_t stoff = sb + 1024 + (uint32_t)emB * PSTG;
#pragma unroll
            for (int i = 0; i < 22; i++) {            // 2048 chunks of 16B = 32KB
                int c = p + i * 96;
                if (c >= 2048) break;
                int reg = c >> 9;                     // 0 Ah, 1 Al, 2 Bh, 3 Bl (512 each)
                int cc = c & 511;
                int row = cc >> 2, kc = cc & 3;       // 4 x 16B per 64B row
                const __nv_bfloat16* T2 = (reg == 0) ? teAh : (reg == 1) ? teAl
                                        : (reg == 2) ? teBh : teBl;
                int r0 = (reg < 2) ? m0 : n0;
                const __nv_bfloat16* src = T2 + (size_t)(r0 + row) * K + k0 + kc * 8;
                uint32_t dst = stoff + (uint32_t)reg * 8192u + SW64SW(row * 64 + kc * 16);
                asm volatile("cp.async.cg.shared.global [%0], [%1], 16;" :: "r"(dst), "l"(src));
            }
            CP_COMMIT();
            emIdx++;
            if (++emB == 3) emB = 0;
            if (++emS == S) {
                emS = 0;
                int nT = -1;
                for (int T2 = emT + gridDim.x; T2 < TT; T2 += gridDim.x) {
                    int e2 = T2 / (gx * gy), r2 = T2 % (gx * gy), y2 = r2 / gx;
                    if (y2 * 128 < g_count[e2]) { nT = T2; break; }
                }
                emT = nT;
            }
        };

        if (emT >= 0) {
            // prime 3 stages (Q = activeTiles*S >= 32 always)
            emitOne(); emitOne(); emitOne();
            asm volatile("cp.async.wait_group 2;" ::: "memory");
            asm volatile("fence.proxy.async.shared::cta;" ::: "memory");
            asm volatile("mbarrier.arrive.shared.b64 _, [%0];" :: "r"(dr[0]) : "memory");

            int sdPh[3] = {0, 0, 0};
            int drsig = 1;                 // (u-2)%3 rolling, u starts at 3 -> (3-2)%3=1
            while (emT >= 0) {
                int b = emB;               // buffer for stage u = emIdx
                MBAR_WAIT(sd[b], sdPh[b]); sdPh[b] ^= 1;   // MMA(u-3) done
                emitOne();                                  // load stage u
                asm volatile("cp.async.wait_group 2;" ::: "memory");  // group u-2 landed
                asm volatile("fence.proxy.async.shared::cta;" ::: "memory");
                asm volatile("mbarrier.arrive.shared.b64 _, [%0];" :: "r"(dr[drsig]) : "memory");
                if (++drsig == 3) drsig = 0;
            }
            // drain: signaled through Q-3; do Q-2, Q-1
            asm volatile("cp.async.wait_group 1;" ::: "memory");
            asm volatile("fence.proxy.async.shared::cta;" ::: "memory");
            asm volatile("mbarrier.arrive.shared.b64 _, [%0];" :: "r"(dr[drsig]) : "memory");
            if (++drsig == 3) drsig = 0;
            asm volatile("cp.async.wait_group 0;" ::: "memory");
            asm volatile("fence.proxy.async.shared::cta;" ::: "memory");
            asm volatile("mbarrier.arrive.shared.b64 _, [%0];" :: "r"(dr[drsig]) : "memory");
        }
    } else {
        // ======== CONSUMERS (warps 0-7) ========
        int tdPh[2] = {0, 0};
        int halfUse = 0;
        int rowgrp = wid & 3;
        int colhalf = wid >> 2;            // 64-col half of the 128-col tile
        for (int T = blockIdx.x; T < TT; T += gridDim.x) {
            int e = T / (gx * gy), r = T % (gx * gy), y = r / gx, x2 = r - y * gx;
            if (y * 128 >= g_count[e]) continue;
            int half = halfUse & 1; halfUse++;
            MBAR_WAIT(td[half], tdPh[half]); tdPh[half] ^= 1;
            asm volatile("tcgen05.fence::after_thread_sync;" ::: "memory");
            int m0 = y * 128, n0 = x2 * 128;
            const float* ebias = bias + (size_t)e * Ntot;
            int m = m0 + rowgrp * 32 + lid;
            uint32_t tb = tmem + (uint32_t)half * 128 + ((uint32_t)rowgrp << 21) + colhalf * 64;
#pragma unroll 1
            for (int ch = 0; ch < 4; ch++) {
                uint32_t rg[16];
                asm volatile("tcgen05.ld.sync.aligned.32x32b.x16.b32 "
                    "{%0, %1, %2, %3, %4, %5, %6, %7, "
                    " %8, %9, %10, %11, %12, %13, %14, %15}, [%16];"
                    : "=r"(rg[0]), "=r"(rg[1]), "=r"(rg[2]), "=r"(rg[3]),
                      "=r"(rg[4]), "=r"(rg[5]), "=r"(rg[6]), "=r"(rg[7]),
                      "=r"(rg[8]), "=r"(rg[9]), "=r"(rg[10]), "=r"(rg[11]),
                      "=r"(rg[12]), "=r"(rg[13]), "=r"(rg[14]), "=r"(rg[15])
                    : "r"(tb + ch * 16));
                asm volatile("tcgen05.wait::ld.sync.aligned;" ::: "memory");
                int nbase = n0 + colhalf * 64 + ch * 16;
                if (mode == 1) {
                    __nv_bfloat16* ph_ = outH + ((size_t)e * CAP + m) * Ntot + nbase;
                    __nv_bfloat16* pl_ = outL + ((size_t)e * CAP + m) * Ntot + nbase;
#pragma unroll
                    for (int j = 0; j < 16; j += 2) {
                        float v0 = __uint_as_float(rg[j])     + ebias[nbase + j];
                        float v1 = __uint_as_float(rg[j + 1]) + ebias[nbase + j + 1];
                        v0 = 0.5f * v0 * (1.f + erff(v0 * 0.70710678118654752f));
                        v1 = 0.5f * v1 * (1.f + erff(v1 * 0.70710678118654752f));
                        __nv_bfloat16 h0 = __float2bfloat16(v0);
                        __nv_bfloat16 h1 = __float2bfloat16(v1);
                        __nv_bfloat16 l0 = __float2bfloat16(v0 - __bfloat162float(h0));
                        __nv_bfloat16 l1 = __float2bfloat16(v1 - __bfloat162float(h1));
                        *(__nv_bfloat162*)(ph_ + j) = __halves2bfloat162(h0, h1);
                        *(__nv_bfloat162*)(pl_ + j) = __halves2bfloat162(l0, l1);
                    }
                } else {
                    float* po = outF + ((size_t)e * CAP + m) * Ntot + nbase;
#pragma unroll
                    for (int j = 0; j < 16; j += 4) {
                        float4 v;
                        v.x = __uint_as_float(rg[j])     + ebias[nbase + j];
                        v.y = __uint_as_float(rg[j + 1]) + ebias[nbase + j + 1];
                        v.z = __uint_as_float(rg[j + 2]) + ebias[nbase + j + 2];
                        v.w = __uint_as_float(rg[j + 3]) + ebias[nbase + j + 3];
                        *(float4*)(po + j) = v;
                    }
                }
            }
            asm volatile("tcgen05.fence::before_thread_sync;" ::: "memory");
            asm volatile("mbarrier.arrive.shared.b64 _, [%0];" :: "r"(tf[half]) : "memory");
        }
    }
    __syncthreads();
    if (wid == 8) {
        asm volatile("tcgen05.relinquish_alloc_permit.cta_group::1.sync.aligned;");
        asm volatile("tcgen05.dealloc.cta_group::1.sync.aligned.b32 %0, 256;" :: "r"(tmem));
    }
#else
    (void)Ah; (void)Al; (void)Bh; (void)Bl; (void)bias;
    (void)outH; (void)outL; (void)outF; (void)K; (void)Ntot; (void)mode;
#endif
}

// ---------------- 5. deterministic combine ----------------
__global__ void combine_kernel(float* __restrict__ out)
{
    int t = blockIdx.x;
    int i0 = g_topi[t * 2 + 0], i1 = g_topi[t * 2 + 1];
    int p0 = g_pos [t * 2 + 0], p1 = g_pos [t * 2 + 1];
    float gv0 = g_gate[t * 2 + 0], gv1 = g_gate[t * 2 + 1];
    float4 acc = make_float4(0.f, 0.f, 0.f, 0.f);
    int d4 = threadIdx.x;
    if (p0 >= 0) {
        float4 a = ((const float4*)(g_out2 + ((size_t)i0 * CAP + p0) * Dd))[d4];
        acc.x += gv0 * a.x; acc.y += gv0 * a.y; acc.z += gv0 * a.z; acc.w += gv0 * a.w;
    }
    if (p1 >= 0) {
        float4 b = ((const float4*)(g_out2 + ((size_t)i1 * CAP + p1) * Dd))[d4];
        acc.x += gv1 * b.x; acc.y += gv1 * b.y; acc.z += gv1 * b.z; acc.w += gv1 * b.w;
    }
    ((float4*)(out + (size_t)t * Dd))[d4] = acc;
}

// ---------------- launch ----------------
extern "C" void kernel_launch(void* const* d_in, const int* in_sizes, int n_in,
                              void* d_out, int out_size)
{
    const float* x     = (const float*)d_in[0];
    const float* noise = (const float*)d_in[1];
    const float* Wg    = (const float*)d_in[2];
    const float* bg    = (const float*)d_in[3];
    const float* Wn    = (const float*)d_in[4];
    const float* bn    = (const float*)d_in[5];
    const float* W1    = (const float*)d_in[6];
    const float* b1    = (const float*)d_in[7];
    const float* W2    = (const float*)d_in[8];
    const float* b2    = (const float*)d_in[9];
    float* out = (float*)d_out;

    const int GEMM_SMEM = 1024 + 3 * 32768;   // 99328 -> 2 CTAs/SM
    cudaFuncSetAttribute(moe_gemm_persist,
                         cudaFuncAttributeMaxDynamicSharedMemorySize, GEMM_SMEM);

    __nv_bfloat16 *xin_h, *xin_l, *w1t_h, *w1t_l, *w2t_h, *w2t_l, *h_h, *h_l;
    float* out2;
    cudaGetSymbolAddress((void**)&xin_h, g_xin_h);
    cudaGetSymbolAddress((void**)&xin_l, g_xin_l);
    cudaGetSymbolAddress((void**)&w1t_h, g_w1t_h);
    cudaGetSymbolAddress((void**)&w1t_l, g_w1t_l);
    cudaGetSymbolAddress((void**)&w2t_h, g_w2t_h);
    cudaGetSymbolAddress((void**)&w2t_l, g_w2t_l);
    cudaGetSymbolAddress((void**)&h_h, g_h_h);
    cudaGetSymbolAddress((void**)&h_l, g_h_l);
    cudaGetSymbolAddress((void**)&out2, g_out2);

    // launches: 1 gating, 2 scan, 3 fused_prep, 4 GEMM1, 5 GEMM2, 6 combine
    gating_kernel<<<F_TOT / 8, 256>>>(x, noise, Wg, bg, Wn, bn);
    scan_kernel<<<Ee, 256>>>();
    fused_prep_kernel<<<65536 + Ee * CAP, 256>>>(W1, W2, x);

    // GEMM1: M=CAP, N=FF, K=D; bias b1; GELU; split-bf16 output
    moe_gemm_persist<<<296, 384, GEMM_SMEM>>>(
        xin_h, xin_l, w1t_h, w1t_l, b1, h_h, h_l, nullptr, Dd, FFf, 1);
    // GEMM2: M=CAP, N=D, K=FF; bias b2; fp32 output
    moe_gemm_persist<<<296, 384, GEMM_SMEM>>>(
        h_h, h_l, w2t_h, w2t_l, b2, nullptr, nullptr, out2, FFf, Dd, 0);

    combine_kernel<<<F_TOT, 256>>>(out);
}

// round 15
// speedup vs baseline: 1.9569x; 1.9569x over previous
#include <cuda_runtime.h>
#include <cuda.h>
#include <cuda_bf16.h>
#include <math.h>
#include <stdint.h>

// ---------------- problem constants ----------------
#define Bb   4
#define Ll   2048
#define Dd   1024
#define Ee   8
#define FFf  4096
#define F_TOT (Bb*Ll)            // 8192
#define CAP   2560               // int(8192*2/8*1.25)

#if defined(__CUDA_ARCH_FEAT_SM103_ALL) || defined(__CUDA_ARCH_SPECIFIC__)
#define HAS_TCGEN05 1
#else
#define HAS_TCGEN05 0
#endif

// ---------------- scratch ----------------
__device__ int   g_topi [F_TOT * 2];
__device__ float g_gate [F_TOT * 2];
__device__ int   g_pos  [F_TOT * 2];
__device__ int   g_disp [Ee * CAP];
__device__ int   g_count[Ee];
__device__ __nv_bfloat16 g_xin_h[(size_t)Ee * CAP * Dd];
__device__ __nv_bfloat16 g_xin_l[(size_t)Ee * CAP * Dd];
__device__ __nv_bfloat16 g_w1t_h[(size_t)Ee * FFf * Dd];
__device__ __nv_bfloat16 g_w1t_l[(size_t)Ee * FFf * Dd];
__device__ __nv_bfloat16 g_w2t_h[(size_t)Ee * Dd * FFf];
__device__ __nv_bfloat16 g_w2t_l[(size_t)Ee * Dd * FFf];
__device__ __nv_bfloat16 g_h_h  [(size_t)Ee * CAP * FFf];
__device__ __nv_bfloat16 g_h_l  [(size_t)Ee * CAP * FFf];
__device__ float         g_out2 [(size_t)Ee * CAP * Dd];

// ---------------- helpers ----------------
__device__ __forceinline__ uint32_t smem_u32(const void* p) {
    uint32_t a;
    asm("{ .reg .u64 t; cvta.to.shared.u64 t, %1; cvt.u32.u64 %0, t; }" : "=r"(a) : "l"(p));
    return a;
}

#define MBAR_WAIT(mbar, par) do {                                             \
    asm volatile("{\n\t.reg .pred P1;\n\t"                                    \
        "WL_%=:\n\t"                                                          \
        "mbarrier.try_wait.parity.acquire.cta.shared::cta.b64 P1, [%0], %1, 0x989680;\n\t" \
        "@P1 bra.uni WD_%=;\n\tbra.uni WL_%=;\n\tWD_%=:\n\t}"                \
        :: "r"(mbar), "r"(par) : "memory");                                   \
} while (0)

// ---------------- 1. gating ----------------
__global__ void gating_kernel(const float* __restrict__ x,
                              const float* __restrict__ noise,
                              const float* __restrict__ Wg, const float* __restrict__ bg,
                              const float* __restrict__ Wn, const float* __restrict__ bn)
{
    int warp = (blockIdx.x * blockDim.x + threadIdx.x) >> 5;
    int lane = threadIdx.x & 31;
    if (warp >= F_TOT) return;
    const float* xr = x + (size_t)warp * Dd;
    float ag[Ee], an[Ee];
#pragma unroll
    for (int e = 0; e < Ee; e++) { ag[e] = 0.f; an[e] = 0.f; }
    for (int d = lane; d < Dd; d += 32) {
        float xv = xr[d];
#pragma unroll
        for (int e = 0; e < Ee; e++) {
            ag[e] = fmaf(xv, Wg[d * Ee + e], ag[e]);
            an[e] = fmaf(xv, Wn[d * Ee + e], an[e]);
        }
    }
#pragma unroll
    for (int off = 16; off > 0; off >>= 1)
#pragma unroll
        for (int e = 0; e < Ee; e++) {
            ag[e] += __shfl_down_sync(0xffffffffu, ag[e], off);
            an[e] += __shfl_down_sync(0xffffffffu, an[e], off);
        }
    if (lane == 0) {
        float noisy[Ee];
#pragma unroll
        for (int e = 0; e < Ee; e++) {
            float l  = ag[e] + bg[e];
            float nl = an[e] + bn[e];
            float sp = fmaxf(nl, 0.f) + log1pf(expf(-fabsf(nl)));
            noisy[e] = l + noise[(size_t)warp * Ee + e] * sp;
        }
        int i0 = 0;
#pragma unroll
        for (int e = 1; e < Ee; e++) if (noisy[e] > noisy[i0]) i0 = e;
        int i1 = -1;
#pragma unroll
        for (int e = 0; e < Ee; e++) {
            if (e == i0) continue;
            if (i1 < 0 || noisy[e] > noisy[i1]) i1 = e;
        }
        float z = expf(noisy[i1] - noisy[i0]);
        float g0 = 1.f / (1.f + z);
        g_topi[warp * 2 + 0] = i0;
        g_topi[warp * 2 + 1] = i1;
        g_gate[warp * 2 + 0] = g0;
        g_gate[warp * 2 + 1] = z * g0;
    }
}

// ---------------- 2. per-expert token-order scan ----------------
__global__ void scan_kernel()
{
    const int e = blockIdx.x;
    const int tid = threadIdx.x;
    __shared__ int sdata[256];
    __shared__ int sbase;
    if (tid == 0) sbase = 0;
    __syncthreads();
    for (int start = 0; start < F_TOT; start += 256) {
        int t = start + tid;
        int i0 = g_topi[t * 2 + 0];
        int i1 = g_topi[t * 2 + 1];
        int m = (i0 == e || i1 == e) ? 1 : 0;
        sdata[tid] = m;
        __syncthreads();
#pragma unroll
        for (int off = 1; off < 256; off <<= 1) {
            int v = (tid >= off) ? sdata[tid - off] : 0;
            __syncthreads();
            sdata[tid] += v;
            __syncthreads();
        }
        int p = sbase + sdata[tid] - 1;
        if (m) {
            int k = (i0 == e) ? 0 : 1;
            if (p < CAP) { g_disp[e * CAP + p] = t; g_pos[t * 2 + k] = p; }
            else         { g_pos[t * 2 + k] = -1; }
        }
        __syncthreads();
        if (tid == 0) sbase += sdata[255];
        __syncthreads();
    }
    if (tid == 0) g_count[e] = min(sbase, CAP);
}

// ---------------- 3. fused prep ----------------
__global__ void fused_prep_kernel(const float* __restrict__ W1, const float* __restrict__ W2,
                                  const float* __restrict__ x)
{
    int id = blockIdx.x;
    if (id < 65536) {
        __shared__ float tile[32][33];
        const float* W; __nv_bfloat16 *Th, *Tl;
        int R, C, bx, by, e;
        if (id < 32768) {
            W = W1; Th = g_w1t_h; Tl = g_w1t_l; R = Dd; C = FFf;
            bx = id & 127; by = (id >> 7) & 31; e = id >> 12;
        } else {
            id -= 32768;
            W = W2; Th = g_w2t_h; Tl = g_w2t_l; R = FFf; C = Dd;
            bx = id & 31; by = (id >> 5) & 127; e = id >> 12;
        }
        int tx = threadIdx.x & 31, ty = threadIdx.x >> 5;
        const float* We = W + (size_t)e * R * C;
        int c = bx * 32 + tx;
#pragma unroll
        for (int j = 0; j < 4; j++) {
            int r = by * 32 + ty + j * 8;
            tile[ty + j * 8][tx] = We[(size_t)r * C + c];
        }
        __syncthreads();
        int r2 = by * 32 + tx;
        size_t ebase = (size_t)e * C * R;
#pragma unroll
        for (int j = 0; j < 4; j++) {
            int c2 = bx * 32 + ty + j * 8;
            float v = tile[tx][ty + j * 8];
            __nv_bfloat16 h = __float2bfloat16(v);
            __nv_bfloat16 l = __float2bfloat16(v - __bfloat162float(h));
            Th[ebase + (size_t)c2 * R + r2] = h;
            Tl[ebase + (size_t)c2 * R + r2] = l;
        }
    } else {
        int gid = id - 65536;
        int e = gid / CAP;
        int c = gid % CAP;
        size_t base = ((size_t)e * CAP + c) * Dd + threadIdx.x * 4;
        if (c < g_count[e]) {
            int t = g_disp[e * CAP + c];
            float4 v = ((const float4*)(x + (size_t)t * Dd))[threadIdx.x];
            float vv[4] = {v.x, v.y, v.z, v.w};
#pragma unroll
            for (int q = 0; q < 4; q += 2) {
                __nv_bfloat16 h0 = __float2bfloat16(vv[q]);
                __nv_bfloat16 h1 = __float2bfloat16(vv[q + 1]);
                __nv_bfloat16 l0 = __float2bfloat16(vv[q] - __bfloat162float(h0));
                __nv_bfloat16 l1 = __float2bfloat16(vv[q + 1] - __bfloat162float(h1));
                *(__nv_bfloat162*)(g_xin_h + base + q) = __halves2bfloat162(h0, h1);
                *(__nv_bfloat162*)(g_xin_l + base + q) = __halves2bfloat162(l0, l1);
            }
        } else {
            __nv_bfloat162 z = __halves2bfloat162(__float2bfloat16(0.f), __float2bfloat16(0.f));
#pragma unroll
            for (int q = 0; q < 4; q += 2) {
                *(__nv_bfloat162*)(g_xin_h + base + q) = z;
                *(__nv_bfloat162*)(g_xin_l + base + q) = z;
            }
        }
    }
}

// ---------------- 4. TMA-fed GEMM: tile 128x256, BK=64, 2 stages x 96KB (SW128) ----------
// stage: Ah(16K)@0 Al(16K)@16384 Bh(32K)@32768 Bl(32K)@65536.
// tid 0 = MMA issuer; tid 32 = TMA issuer; all 8 warps do the epilogue.
// header: [0] tmem; full[2]@16/24 (TMA complete_tx, cnt1); sd[2]@32/40 (MMA done, cnt1);
//         td@48 (tile done, cnt1).
#define TSTG 98304u

__global__ void __launch_bounds__(256, 1)
moe_gemm_tma(const __grid_constant__ CUtensorMap tAh,
             const __grid_constant__ CUtensorMap tAl,
             const __grid_constant__ CUtensorMap tBh,
             const __grid_constant__ CUtensorMap tBl,
             const float* __restrict__ bias,
             __nv_bfloat16* __restrict__ outH, __nv_bfloat16* __restrict__ outL,
             float* __restrict__ outF,
             int K, int Ntot, int mode)
{
#if HAS_TCGEN05
    extern __shared__ __align__(1024) char smem[];
    int e = blockIdx.z;
    int m0 = blockIdx.y * 128;
    if (m0 >= g_count[e]) return;
    int n0 = blockIdx.x * 256;
    int tid = threadIdx.x;
    int wid = tid >> 5, lid = tid & 31;
    const int S = K >> 6;

    uint32_t sb = smem_u32(smem);
    uint32_t full[2] = {sb + 16, sb + 24};
    uint32_t sd[2]   = {sb + 32, sb + 40};
    uint32_t td      = sb + 48;
    if (tid == 0) {
#pragma unroll
        for (int b = 0; b < 2; b++) {
            asm volatile("mbarrier.init.shared.b64 [%0], 1;" :: "r"(full[b]) : "memory");
            asm volatile("mbarrier.init.shared.b64 [%0], 1;" :: "r"(sd[b]) : "memory");
        }
        asm volatile("mbarrier.init.shared.b64 [%0], 1;" :: "r"(td) : "memory");
    }
    if (wid == 0)
        asm volatile("tcgen05.alloc.cta_group::1.sync.aligned.shared::cta.b32 [%0], 256;"
                     :: "r"(sb) : "memory");
    __syncthreads();
    uint32_t tmem;
    asm volatile("ld.shared.b32 %0, [%1];" : "=r"(tmem) : "r"(sb));

    if (tid == 32) {
        // ======== TMA issuer ========
        auto issueStage = [&](int u) {
            uint32_t st = sb + 1024 + (uint32_t)(u & 1) * TSTG;
            uint32_t mb = full[u & 1];
            asm volatile("mbarrier.arrive.expect_tx.shared.b64 _, [%0], %1;"
                         :: "r"(mb), "r"(98304u) : "memory");
            int k0 = u * 64;
            asm volatile("cp.async.bulk.tensor.3d.shared::cta.global.tile.mbarrier::complete_tx::bytes "
                "[%0], [%1, {%2, %3, %4}], [%5];"
                :: "r"(st), "l"((uint64_t)&tAh), "r"(k0), "r"(m0), "r"(e), "r"(mb) : "memory");
            asm volatile("cp.async.bulk.tensor.3d.shared::cta.global.tile.mbarrier::complete_tx::bytes "
                "[%0], [%1, {%2, %3, %4}], [%5];"
                :: "r"(st + 16384u), "l"((uint64_t)&tAl), "r"(k0), "r"(m0), "r"(e), "r"(mb) : "memory");
            asm volatile("cp.async.bulk.tensor.3d.shared::cta.global.tile.mbarrier::complete_tx::bytes "
                "[%0], [%1, {%2, %3, %4}], [%5];"
                :: "r"(st + 32768u), "l"((uint64_t)&tBh), "r"(k0), "r"(n0), "r"(e), "r"(mb) : "memory");
            asm volatile("cp.async.bulk.tensor.3d.shared::cta.global.tile.mbarrier::complete_tx::bytes "
                "[%0], [%1, {%2, %3, %4}], [%5];"
                :: "r"(st + 65536u), "l"((uint64_t)&tBl), "r"(k0), "r"(n0), "r"(e), "r"(mb) : "memory");
        };
        issueStage(0);
        if (S > 1) issueStage(1);
        int sdPh[2] = {0, 0};
        for (int u = 2; u < S; u++) {
            int b = u & 1;
            MBAR_WAIT(sd[b], sdPh[b]); sdPh[b] ^= 1;   // MMA(u-2) retired -> buffer free
            issueStage(u);
        }
    } else if (tid == 0) {
        // ======== MMA issuer ========
        const uint32_t IDESC = (8u << 24) | (32u << 17) | (1u << 10) | (1u << 7) | (1u << 4);
        const uint64_t DB = ((uint64_t)2 << 61) | ((uint64_t)1 << 46) |
                            ((uint64_t)64 << 32) | ((uint64_t)1 << 16);
        int fuPh[2] = {0, 0};
        for (int s = 0; s < S; s++) {
            int b = s & 1;
            MBAR_WAIT(full[b], fuPh[b]); fuPh[b] ^= 1;
            uint32_t st = sb + 1024 + (uint32_t)b * TSTG;
            uint64_t dAh = DB | ((st >> 4) & 0x3FFF);
            uint64_t dAl = DB | (((st + 16384u) >> 4) & 0x3FFF);
            uint64_t dBh = DB | (((st + 32768u) >> 4) & 0x3FFF);
            uint64_t dBl = DB | (((st + 65536u) >> 4) & 0x3FFF);
#pragma unroll
            for (int kc = 0; kc < 4; kc++) {
                uint32_t en = (s | kc) != 0;
                asm volatile("{ .reg .pred p; setp.ne.u32 p, %4, 0;\n\t"
                    "tcgen05.mma.cta_group::1.kind::f16 [%0], %1, %2, %3, {%5,%5,%5,%5}, p; }"
                    :: "r"(tmem), "l"(dAh + kc * 2), "l"(dBh + kc * 2), "r"(IDESC),
                       "r"(en), "r"(0u) : "memory");
            }
#pragma unroll
            for (int kc = 0; kc < 4; kc++)
                asm volatile("{ .reg .pred p; setp.ne.u32 p, 1, 0;\n\t"
                    "tcgen05.mma.cta_group::1.kind::f16 [%0], %1, %2, %3, {%4,%4,%4,%4}, p; }"
                    :: "r"(tmem), "l"(dAh + kc * 2), "l"(dBl + kc * 2), "r"(IDESC), "r"(0u) : "memory");
#pragma unroll
            for (int kc = 0; kc < 4; kc++)
                asm volatile("{ .reg .pred p; setp.ne.u32 p, 1, 0;\n\t"
                    "tcgen05.mma.cta_group::1.kind::f16 [%0], %1, %2, %3, {%4,%4,%4,%4}, p; }"
                    :: "r"(tmem), "l"(dAl + kc * 2), "l"(dBh + kc * 2), "r"(IDESC), "r"(0u) : "memory");
            asm volatile("tcgen05.commit.cta_group::1.mbarrier::arrive::one.shared::cluster.b64 [%0];"
                         :: "r"(sd[b]) : "memory");
            if (s == S - 1)
                asm volatile("tcgen05.commit.cta_group::1.mbarrier::arrive::one.shared::cluster.b64 [%0];"
                             :: "r"(td) : "memory");
        }
    }

    // ======== all threads: wait tile completion, then epilogue ========
    MBAR_WAIT(td, 0);
    asm volatile("tcgen05.fence::after_thread_sync;" ::: "memory");
    {
        int rowgrp = wid & 3;
        int colhalf = wid >> 2;
        uint32_t woff = (uint32_t)rowgrp << 21;
        int m = m0 + rowgrp * 32 + lid;
        const float* ebias = bias + (size_t)e * Ntot;
#pragma unroll 1
        for (int ch = 0; ch < 4; ch++) {
            uint32_t rg[32];
            asm volatile("tcgen05.ld.sync.aligned.32x32b.x32.b32 "
                "{%0, %1, %2, %3, %4, %5, %6, %7, "
                " %8, %9, %10, %11, %12, %13, %14, %15, "
                " %16, %17, %18, %19, %20, %21, %22, %23, "
                " %24, %25, %26, %27, %28, %29, %30, %31}, [%32];"
                : "=r"(rg[0]), "=r"(rg[1]), "=r"(rg[2]), "=r"(rg[3]),
                  "=r"(rg[4]), "=r"(rg[5]), "=r"(rg[6]), "=r"(rg[7]),
                  "=r"(rg[8]), "=r"(rg[9]), "=r"(rg[10]), "=r"(rg[11]),
                  "=r"(rg[12]), "=r"(rg[13]), "=r"(rg[14]), "=r"(rg[15]),
                  "=r"(rg[16]), "=r"(rg[17]), "=r"(rg[18]), "=r"(rg[19]),
                  "=r"(rg[20]), "=r"(rg[21]), "=r"(rg[22]), "=r"(rg[23]),
                  "=r"(rg[24]), "=r"(rg[25]), "=r"(rg[26]), "=r"(rg[27]),
                  "=r"(rg[28]), "=r"(rg[29]), "=r"(rg[30]), "=r"(rg[31])
                : "r"(tmem + woff + colhalf * 128 + ch * 32));
            asm volatile("tcgen05.wait::ld.sync.aligned;" ::: "memory");
            int nbase = n0 + colhalf * 128 + ch * 32;
            if (mode == 1) {
                __nv_bfloat16* ph_ = outH + ((size_t)e * CAP + m) * Ntot + nbase;
                __nv_bfloat16* pl_ = outL + ((size_t)e * CAP + m) * Ntot + nbase;
#pragma unroll
                for (int j = 0; j < 32; j += 2) {
                    float v0 = __uint_as_float(rg[j])     + ebias[nbase + j];
                    float v1 = __uint_as_float(rg[j + 1]) + ebias[nbase + j + 1];
                    v0 = 0.5f * v0 * (1.f + erff(v0 * 0.70710678118654752f));
                    v1 = 0.5f * v1 * (1.f + erff(v1 * 0.70710678118654752f));
                    __nv_bfloat16 h0 = __float2bfloat16(v0);
                    __nv_bfloat16 h1 = __float2bfloat16(v1);
                    __nv_bfloat16 l0 = __float2bfloat16(v0 - __bfloat162float(h0));
                    __nv_bfloat16 l1 = __float2bfloat16(v1 - __bfloat162float(h1));
                    *(__nv_bfloat162*)(ph_ + j) = __halves2bfloat162(h0, h1);
                    *(__nv_bfloat162*)(pl_ + j) = __halves2bfloat162(l0, l1);
                }
            } else {
                float* po = outF + ((size_t)e * CAP + m) * Ntot + nbase;
#pragma unroll
                for (int j = 0; j < 32; j += 4) {
                    float4 v;
                    v.x = __uint_as_float(rg[j])     + ebias[nbase + j];
                    v.y = __uint_as_float(rg[j + 1]) + ebias[nbase + j + 1];
                    v.z = __uint_as_float(rg[j + 2]) + ebias[nbase + j + 2];
                    v.w = __uint_as_float(rg[j + 3]) + ebias[nbase + j + 3];
                    *(float4*)(po + j) = v;
                }
            }
        }
    }
    __syncthreads();
    if (wid == 0) {
        asm volatile("tcgen05.relinquish_alloc_permit.cta_group::1.sync.aligned;");
        asm volatile("tcgen05.dealloc.cta_group::1.sync.aligned.b32 %0, 256;" :: "r"(tmem));
    }
#else
    (void)tAh; (void)tAl; (void)tBh; (void)tBl; (void)bias;
    (void)outH; (void)outL; (void)outF; (void)K; (void)Ntot; (void)mode;
#endif
}

// ---------------- 5. deterministic combine ----------------
__global__ void combine_kernel(float* __restrict__ out)
{
    int t = blockIdx.x;
    int i0 = g_topi[t * 2 + 0], i1 = g_topi[t * 2 + 1];
    int p0 = g_pos [t * 2 + 0], p1 = g_pos [t * 2 + 1];
    float gv0 = g_gate[t * 2 + 0], gv1 = g_gate[t * 2 + 1];
    float4 acc = make_float4(0.f, 0.f, 0.f, 0.f);
    int d4 = threadIdx.x;
    if (p0 >= 0) {
        float4 a = ((const float4*)(g_out2 + ((size_t)i0 * CAP + p0) * Dd))[d4];
        acc.x += gv0 * a.x; acc.y += gv0 * a.y; acc.z += gv0 * a.z; acc.w += gv0 * a.w;
    }
    if (p1 >= 0) {
        float4 b = ((const float4*)(g_out2 + ((size_t)i1 * CAP + p1) * Dd))[d4];
        acc.x += gv1 * b.x; acc.y += gv1 * b.y; acc.z += gv1 * b.z; acc.w += gv1 * b.w;
    }
    ((float4*)(out + (size_t)t * Dd))[d4] = acc;
}

// ---------------- host: tensormap encoding via driver entry point ----------------
typedef CUresult (*EncodeFn)(CUtensorMap*, CUtensorMapDataType, cuuint32_t, void*,
                             const cuuint64_t*, const cuuint64_t*, const cuuint32_t*,
                             const cuuint32_t*, CUtensorMapInterleave, CUtensorMapSwizzle,
                             CUtensorMapL2promotion, CUtensorMapFloatOOBfill);

static void encode3d(EncodeFn enc, CUtensorMap* tm, void* ptr,
                     uint64_t kdim, uint64_t rows, uint32_t boxRows)
{
    cuuint64_t dims[3]    = {kdim, rows, (cuuint64_t)Ee};
    cuuint64_t strides[2] = {kdim * 2, (cuuint64_t)rows * kdim * 2};
    cuuint32_t box[3]     = {64, boxRows, 1};
    cuuint32_t estr[3]    = {1, 1, 1};
    enc(tm, CU_TENSOR_MAP_DATA_TYPE_BFLOAT16, 3, ptr, dims, strides, box, estr,
        CU_TENSOR_MAP_INTERLEAVE_NONE, CU_TENSOR_MAP_SWIZZLE_128B,
        CU_TENSOR_MAP_L2_PROMOTION_L2_128B, CU_TENSOR_MAP_FLOAT_OOB_FILL_NONE);
}

// ---------------- launch ----------------
extern "C" void kernel_launch(void* const* d_in, const int* in_sizes, int n_in,
                              void* d_out, int out_size)
{
    const float* x     = (const float*)d_in[0];
    const float* noise = (const float*)d_in[1];
    const float* Wg    = (const float*)d_in[2];
    const float* bg    = (const float*)d_in[3];
    const float* Wn    = (const float*)d_in[4];
    const float* bn    = (const float*)d_in[5];
    const float* W1    = (const float*)d_in[6];
    const float* b1    = (const float*)d_in[7];
    const float* W2    = (const float*)d_in[8];
    const float* b2    = (const float*)d_in[9];
    float* out = (float*)d_out;

    const int GEMM_SMEM = 1024 + 2 * 98304;   // 197632
    cudaFuncSetAttribute(moe_gemm_tma,
                         cudaFuncAttributeMaxDynamicSharedMemorySize, GEMM_SMEM);

    __nv_bfloat16 *xin_h, *xin_l, *w1t_h, *w1t_l, *w2t_h, *w2t_l, *h_h, *h_l;
    float* out2;
    cudaGetSymbolAddress((void**)&xin_h, g_xin_h);
    cudaGetSymbolAddress((void**)&xin_l, g_xin_l);
    cudaGetSymbolAddress((void**)&w1t_h, g_w1t_h);
    cudaGetSymbolAddress((void**)&w1t_l, g_w1t_l);
    cudaGetSymbolAddress((void**)&w2t_h, g_w2t_h);
    cudaGetSymbolAddress((void**)&w2t_l, g_w2t_l);
    cudaGetSymbolAddress((void**)&h_h, g_h_h);
    cudaGetSymbolAddress((void**)&h_l, g_h_l);
    cudaGetSymbolAddress((void**)&out2, g_out2);

    EncodeFn enc = nullptr;
    cudaDriverEntryPointQueryResult qr;
    cudaGetDriverEntryPoint("cuTensorMapEncodeTiled", (void**)&enc,
                            cudaEnableDefault, &qr);

    CUtensorMap t1Ah, t1Al, t1Bh, t1Bl, t2Ah, t2Al, t2Bh, t2Bl;
    // GEMM1: A = xin [E, CAP, D], B = w1t [E, FF, D]
    encode3d(enc, &t1Ah, xin_h, Dd, CAP, 128);
    encode3d(enc, &t1Al, xin_l, Dd, CAP, 128);
    encode3d(enc, &t1Bh, w1t_h, Dd, FFf, 256);
    encode3d(enc, &t1Bl, w1t_l, Dd, FFf, 256);
    // GEMM2: A = h [E, CAP, FF], B = w2t [E, D, FF]
    encode3d(enc, &t2Ah, h_h, FFf, CAP, 128);
    encode3d(enc, &t2Al, h_l, FFf, CAP, 128);
    encode3d(enc, &t2Bh, w2t_h, FFf, Dd, 256);
    encode3d(enc, &t2Bl, w2t_l, FFf, Dd, 256);

    // launches: 1 gating, 2 scan, 3 fused_prep, 4 GEMM1, 5 GEMM2, 6 combine
    gating_kernel<<<F_TOT / 8, 256>>>(x, noise, Wg, bg, Wn, bn);
    scan_kernel<<<Ee, 256>>>();
    fused_prep_kernel<<<65536 + Ee * CAP, 256>>>(W1, W2, x);

    // GEMM1: M=CAP, N=FF, K=D; bias b1; GELU; split-bf16 output
    moe_gemm_tma<<<dim3(FFf / 256, CAP / 128, Ee), 256, GEMM_SMEM>>>(
        t1Ah, t1Al, t1Bh, t1Bl, b1, h_h, h_l, nullptr, Dd, FFf, 1);
    // GEMM2: M=CAP, N=D, K=FF; bias b2; fp32 output
    moe_gemm_tma<<<dim3(Dd / 256, CAP / 128, Ee), 256, GEMM_SMEM>>>(
        t2Ah, t2Al, t2Bh, t2Bl, b2, nullptr, nullptr, out2, FFf, Dd, 0);

    combine_kernel<<<F_TOT, 256>>>(out);
}

// round 16
// speedup vs baseline: 2.0033x; 1.0237x over previous
#include <cuda_runtime.h>
#include <cuda.h>
#include <cuda_bf16.h>
#include <math.h>
#include <stdint.h>

// ---------------- problem constants ----------------
#define Bb   4
#define Ll   2048
#define Dd   1024
#define Ee   8
#define FFf  4096
#define F_TOT (Bb*Ll)            // 8192
#define CAP   2560               // int(8192*2/8*1.25)

#if defined(__CUDA_ARCH_FEAT_SM103_ALL) || defined(__CUDA_ARCH_SPECIFIC__)
#define HAS_TCGEN05 1
#else
#define HAS_TCGEN05 0
#endif

// ---------------- scratch ----------------
__device__ int   g_topi [F_TOT * 2];
__device__ float g_gate [F_TOT * 2];
__device__ int   g_pos  [F_TOT * 2];
__device__ int   g_disp [Ee * CAP];
__device__ int   g_count[Ee];
__device__ __nv_bfloat16 g_xin_h[(size_t)Ee * CAP * Dd];
__device__ __nv_bfloat16 g_xin_l[(size_t)Ee * CAP * Dd];
__device__ __nv_bfloat16 g_w1t_h[(size_t)Ee * FFf * Dd];
__device__ __nv_bfloat16 g_w1t_l[(size_t)Ee * FFf * Dd];
__device__ __nv_bfloat16 g_w2t_h[(size_t)Ee * Dd * FFf];
__device__ __nv_bfloat16 g_w2t_l[(size_t)Ee * Dd * FFf];
__device__ __nv_bfloat16 g_h_h  [(size_t)Ee * CAP * FFf];
__device__ __nv_bfloat16 g_h_l  [(size_t)Ee * CAP * FFf];
__device__ float         g_out2 [(size_t)Ee * CAP * Dd];

// ---------------- helpers ----------------
__device__ __forceinline__ uint32_t smem_u32(const void* p) {
    uint32_t a;
    asm("{ .reg .u64 t; cvta.to.shared.u64 t, %1; cvt.u32.u64 %0, t; }" : "=r"(a) : "l"(p));
    return a;
}

#define MBAR_WAIT(mbar, par) do {                                             \
    asm volatile("{\n\t.reg .pred P1;\n\t"                                    \
        "WL_%=:\n\t"                                                          \
        "mbarrier.try_wait.parity.acquire.cta.shared::cta.b64 P1, [%0], %1, 0x989680;\n\t" \
        "@P1 bra.uni WD_%=;\n\tbra.uni WL_%=;\n\tWD_%=:\n\t}"                \
        :: "r"(mbar), "r"(par) : "memory");                                   \
} while (0)

// ---------------- 1. gating ----------------
__global__ void gating_kernel(const float* __restrict__ x,
                              const float* __restrict__ noise,
                              const float* __restrict__ Wg, const float* __restrict__ bg,
                              const float* __restrict__ Wn, const float* __restrict__ bn)
{
    int warp = (blockIdx.x * blockDim.x + threadIdx.x) >> 5;
    int lane = threadIdx.x & 31;
    if (warp >= F_TOT) return;
    const float* xr = x + (size_t)warp * Dd;
    float ag[Ee], an[Ee];
#pragma unroll
    for (int e = 0; e < Ee; e++) { ag[e] = 0.f; an[e] = 0.f; }
    for (int d = lane; d < Dd; d += 32) {
        float xv = xr[d];
#pragma unroll
        for (int e = 0; e < Ee; e++) {
            ag[e] = fmaf(xv, Wg[d * Ee + e], ag[e]);
            an[e] = fmaf(xv, Wn[d * Ee + e], an[e]);
        }
    }
#pragma unroll
    for (int off = 16; off > 0; off >>= 1)
#pragma unroll
        for (int e = 0; e < Ee; e++) {
            ag[e] += __shfl_down_sync(0xffffffffu, ag[e], off);
            an[e] += __shfl_down_sync(0xffffffffu, an[e], off);
        }
    if (lane == 0) {
        float noisy[Ee];
#pragma unroll
        for (int e = 0; e < Ee; e++) {
            float l  = ag[e] + bg[e];
            float nl = an[e] + bn[e];
            float sp = fmaxf(nl, 0.f) + log1pf(expf(-fabsf(nl)));
            noisy[e] = l + noise[(size_t)warp * Ee + e] * sp;
        }
        int i0 = 0;
#pragma unroll
        for (int e = 1; e < Ee; e++) if (noisy[e] > noisy[i0]) i0 = e;
        int i1 = -1;
#pragma unroll
        for (int e = 0; e < Ee; e++) {
            if (e == i0) continue;
            if (i1 < 0 || noisy[e] > noisy[i1]) i1 = e;
        }
        float z = expf(noisy[i1] - noisy[i0]);
        float g0 = 1.f / (1.f + z);
        g_topi[warp * 2 + 0] = i0;
        g_topi[warp * 2 + 1] = i1;
        g_gate[warp * 2 + 0] = g0;
        g_gate[warp * 2 + 1] = z * g0;
    }
}

// ---------------- 2. per-expert token-order scan ----------------
__global__ void scan_kernel()
{
    const int e = blockIdx.x;
    const int tid = threadIdx.x;
    __shared__ int sdata[256];
    __shared__ int sbase;
    if (tid == 0) sbase = 0;
    __syncthreads();
    for (int start = 0; start < F_TOT; start += 256) {
        int t = start + tid;
        int i0 = g_topi[t * 2 + 0];
        int i1 = g_topi[t * 2 + 1];
        int m = (i0 == e || i1 == e) ? 1 : 0;
        sdata[tid] = m;
        __syncthreads();
#pragma unroll
        for (int off = 1; off < 256; off <<= 1) {
            int v = (tid >= off) ? sdata[tid - off] : 0;
            __syncthreads();
            sdata[tid] += v;
            __syncthreads();
        }
        int p = sbase + sdata[tid] - 1;
        if (m) {
            int k = (i0 == e) ? 0 : 1;
            if (p < CAP) { g_disp[e * CAP + p] = t; g_pos[t * 2 + k] = p; }
            else         { g_pos[t * 2 + k] = -1; }
        }
        __syncthreads();
        if (tid == 0) sbase += sdata[255];
        __syncthreads();
    }
    if (tid == 0) g_count[e] = min(sbase, CAP);
}

// ---------------- 3. fused prep ----------------
__global__ void fused_prep_kernel(const float* __restrict__ W1, const float* __restrict__ W2,
                                  const float* __restrict__ x)
{
    int id = blockIdx.x;
    if (id < 65536) {
        __shared__ float tile[32][33];
        const float* W; __nv_bfloat16 *Th, *Tl;
        int R, C, bx, by, e;
        if (id < 32768) {
            W = W1; Th = g_w1t_h; Tl = g_w1t_l; R = Dd; C = FFf;
            bx = id & 127; by = (id >> 7) & 31; e = id >> 12;
        } else {
            id -= 32768;
            W = W2; Th = g_w2t_h; Tl = g_w2t_l; R = FFf; C = Dd;
            bx = id & 31; by = (id >> 5) & 127; e = id >> 12;
        }
        int tx = threadIdx.x & 31, ty = threadIdx.x >> 5;
        const float* We = W + (size_t)e * R * C;
        int c = bx * 32 + tx;
#pragma unroll
        for (int j = 0; j < 4; j++) {
            int r = by * 32 + ty + j * 8;
            tile[ty + j * 8][tx] = We[(size_t)r * C + c];
        }
        __syncthreads();
        int r2 = by * 32 + tx;
        size_t ebase = (size_t)e * C * R;
#pragma unroll
        for (int j = 0; j < 4; j++) {
            int c2 = bx * 32 + ty + j * 8;
            float v = tile[tx][ty + j * 8];
            __nv_bfloat16 h = __float2bfloat16(v);
            __nv_bfloat16 l = __float2bfloat16(v - __bfloat162float(h));
            Th[ebase + (size_t)c2 * R + r2] = h;
            Tl[ebase + (size_t)c2 * R + r2] = l;
        }
    } else {
        int gid = id - 65536;
        int e = gid / CAP;
        int c = gid % CAP;
        size_t base = ((size_t)e * CAP + c) * Dd + threadIdx.x * 4;
        if (c < g_count[e]) {
            int t = g_disp[e * CAP + c];
            float4 v = ((const float4*)(x + (size_t)t * Dd))[threadIdx.x];
            float vv[4] = {v.x, v.y, v.z, v.w};
#pragma unroll
            for (int q = 0; q < 4; q += 2) {
                __nv_bfloat16 h0 = __float2bfloat16(vv[q]);
                __nv_bfloat16 h1 = __float2bfloat16(vv[q + 1]);
                __nv_bfloat16 l0 = __float2bfloat16(vv[q] - __bfloat162float(h0));
                __nv_bfloat16 l1 = __float2bfloat16(vv[q + 1] - __bfloat162float(h1));
                *(__nv_bfloat162*)(g_xin_h + base + q) = __halves2bfloat162(h0, h1);
                *(__nv_bfloat162*)(g_xin_l + base + q) = __halves2bfloat162(l0, l1);
            }
        } else {
            __nv_bfloat162 z = __halves2bfloat162(__float2bfloat16(0.f), __float2bfloat16(0.f));
#pragma unroll
            for (int q = 0; q < 4; q += 2) {
                *(__nv_bfloat162*)(g_xin_h + base + q) = z;
                *(__nv_bfloat162*)(g_xin_l + base + q) = z;
            }
        }
    }
}

// ---------------- 4. TMA-fed GEMM: tile 128x256, BK=32, 4 stages x 48KB (SW64) ----------
// stage: Ah(8K)@0 Al(8K)@8192 Bh(16K)@16384 Bl(16K)@32768.
// tid 0 = MMA issuer; tid 32 = TMA issuer; all 8 warps epilogue.
// header: [0] tmem; full[4]@16..40 (TMA complete_tx, cnt1); sd[4]@48..72 (MMA done, cnt1);
//         td@80 (tile done, cnt1).
#define TSTG 49152u

__global__ void __launch_bounds__(256, 1)
moe_gemm_tma(const __grid_constant__ CUtensorMap tAh,
             const __grid_constant__ CUtensorMap tAl,
             const __grid_constant__ CUtensorMap tBh,
             const __grid_constant__ CUtensorMap tBl,
             const float* __restrict__ bias,
             __nv_bfloat16* __restrict__ outH, __nv_bfloat16* __restrict__ outL,
             float* __restrict__ outF,
             int K, int Ntot, int mode)
{
#if HAS_TCGEN05
    extern __shared__ __align__(1024) char smem[];
    int e = blockIdx.z;
    int m0 = blockIdx.y * 128;
    if (m0 >= g_count[e]) return;
    int n0 = blockIdx.x * 256;
    int tid = threadIdx.x;
    int wid = tid >> 5, lid = tid & 31;
    const int S = K >> 5;                 // BK=32

    uint32_t sb = smem_u32(smem);
    uint32_t full[4] = {sb + 16, sb + 24, sb + 32, sb + 40};
    uint32_t sd[4]   = {sb + 48, sb + 56, sb + 64, sb + 72};
    uint32_t td      = sb + 80;
    if (tid == 0) {
#pragma unroll
        for (int b = 0; b < 4; b++) {
            asm volatile("mbarrier.init.shared.b64 [%0], 1;" :: "r"(full[b]) : "memory");
            asm volatile("mbarrier.init.shared.b64 [%0], 1;" :: "r"(sd[b]) : "memory");
        }
        asm volatile("mbarrier.init.shared.b64 [%0], 1;" :: "r"(td) : "memory");
    }
    if (wid == 0)
        asm volatile("tcgen05.alloc.cta_group::1.sync.aligned.shared::cta.b32 [%0], 256;"
                     :: "r"(sb) : "memory");
    __syncthreads();
    uint32_t tmem;
    asm volatile("ld.shared.b32 %0, [%1];" : "=r"(tmem) : "r"(sb));

    if (tid == 32) {
        // ======== TMA issuer ========
        auto issueStage = [&](int u) {
            uint32_t st = sb + 1024 + (uint32_t)(u & 3) * TSTG;
            uint32_t mb = full[u & 3];
            asm volatile("mbarrier.arrive.expect_tx.shared.b64 _, [%0], %1;"
                         :: "r"(mb), "r"(49152u) : "memory");
            int k0 = u * 32;
            asm volatile("cp.async.bulk.tensor.3d.shared::cta.global.tile.mbarrier::complete_tx::bytes "
                "[%0], [%1, {%2, %3, %4}], [%5];"
                :: "r"(st), "l"((uint64_t)&tAh), "r"(k0), "r"(m0), "r"(e), "r"(mb) : "memory");
            asm volatile("cp.async.bulk.tensor.3d.shared::cta.global.tile.mbarrier::complete_tx::bytes "
                "[%0], [%1, {%2, %3, %4}], [%5];"
                :: "r"(st + 8192u), "l"((uint64_t)&tAl), "r"(k0), "r"(m0), "r"(e), "r"(mb) : "memory");
            asm volatile("cp.async.bulk.tensor.3d.shared::cta.global.tile.mbarrier::complete_tx::bytes "
                "[%0], [%1, {%2, %3, %4}], [%5];"
                :: "r"(st + 16384u), "l"((uint64_t)&tBh), "r"(k0), "r"(n0), "r"(e), "r"(mb) : "memory");
            asm volatile("cp.async.bulk.tensor.3d.shared::cta.global.tile.mbarrier::complete_tx::bytes "
                "[%0], [%1, {%2, %3, %4}], [%5];"
                :: "r"(st + 32768u), "l"((uint64_t)&tBl), "r"(k0), "r"(n0), "r"(e), "r"(mb) : "memory");
        };
        issueStage(0); issueStage(1); issueStage(2); issueStage(3);
        int sdPh[4] = {0, 0, 0, 0};
        for (int u = 4; u < S; u++) {
            int b = u & 3;
            MBAR_WAIT(sd[b], sdPh[b]); sdPh[b] ^= 1;   // MMA(u-4) retired -> buffer free
            issueStage(u);
        }
    } else if (tid == 0) {
        // ======== MMA issuer ========
        const uint32_t IDESC = (8u << 24) | (32u << 17) | (1u << 10) | (1u << 7) | (1u << 4);
        // SW64 descriptor base: layout=4, version=1, SBO=32 (512B), LBO=1 (16B)  [R13-proven]
        const uint64_t DB = ((uint64_t)4 << 61) | ((uint64_t)1 << 46) |
                            ((uint64_t)32 << 32) | ((uint64_t)1 << 16);
        int fuPh[4] = {0, 0, 0, 0};
        for (int s = 0; s < S; s++) {
            int b = s & 3;
            MBAR_WAIT(full[b], fuPh[b]); fuPh[b] ^= 1;
            uint32_t st = sb + 1024 + (uint32_t)b * TSTG;
            uint64_t dAh = DB | ((st >> 4) & 0x3FFF);
            uint64_t dAl = DB | (((st + 8192u) >> 4) & 0x3FFF);
            uint64_t dBh = DB | (((st + 16384u) >> 4) & 0x3FFF);
            uint64_t dBl = DB | (((st + 32768u) >> 4) & 0x3FFF);
#pragma unroll
            for (int kc = 0; kc < 2; kc++) {
                uint32_t en = (s | kc) != 0;
                asm volatile("{ .reg .pred p; setp.ne.u32 p, %4, 0;\n\t"
                    "tcgen05.mma.cta_group::1.kind::f16 [%0], %1, %2, %3, {%5,%5,%5,%5}, p; }"
                    :: "r"(tmem), "l"(dAh + kc * 2), "l"(dBh + kc * 2), "r"(IDESC),
                       "r"(en), "r"(0u) : "memory");
            }
#pragma unroll
            for (int kc = 0; kc < 2; kc++)
                asm volatile("{ .reg .pred p; setp.ne.u32 p, 1, 0;\n\t"
                    "tcgen05.mma.cta_group::1.kind::f16 [%0], %1, %2, %3, {%4,%4,%4,%4}, p; }"
                    :: "r"(tmem), "l"(dAh + kc * 2), "l"(dBl + kc * 2), "r"(IDESC), "r"(0u) : "memory");
#pragma unroll
            for (int kc = 0; kc < 2; kc++)
                asm volatile("{ .reg .pred p; setp.ne.u32 p, 1, 0;\n\t"
                    "tcgen05.mma.cta_group::1.kind::f16 [%0], %1, %2, %3, {%4,%4,%4,%4}, p; }"
                    :: "r"(tmem), "l"(dAl + kc * 2), "l"(dBh + kc * 2), "r"(IDESC), "r"(0u) : "memory");
            asm volatile("tcgen05.commit.cta_group::1.mbarrier::arrive::one.shared::cluster.b64 [%0];"
                         :: "r"(sd[b]) : "memory");
            if (s == S - 1)
                asm volatile("tcgen05.commit.cta_group::1.mbarrier::arrive::one.shared::cluster.b64 [%0];"
                             :: "r"(td) : "memory");
        }
    }

    // ======== all threads: wait tile completion, then epilogue ========
    MBAR_WAIT(td, 0);
    asm volatile("tcgen05.fence::after_thread_sync;" ::: "memory");
    {
        int rowgrp = wid & 3;
        int colhalf = wid >> 2;
        uint32_t woff = (uint32_t)rowgrp << 21;
        int m = m0 + rowgrp * 32 + lid;
        const float* ebias = bias + (size_t)e * Ntot;
#pragma unroll 1
        for (int ch = 0; ch < 4; ch++) {
            uint32_t rg[32];
            asm volatile("tcgen05.ld.sync.aligned.32x32b.x32.b32 "
                "{%0, %1, %2, %3, %4, %5, %6, %7, "
                " %8, %9, %10, %11, %12, %13, %14, %15, "
                " %16, %17, %18, %19, %20, %21, %22, %23, "
                " %24, %25, %26, %27, %28, %29, %30, %31}, [%32];"
                : "=r"(rg[0]), "=r"(rg[1]), "=r"(rg[2]), "=r"(rg[3]),
                  "=r"(rg[4]), "=r"(rg[5]), "=r"(rg[6]), "=r"(rg[7]),
                  "=r"(rg[8]), "=r"(rg[9]), "=r"(rg[10]), "=r"(rg[11]),
                  "=r"(rg[12]), "=r"(rg[13]), "=r"(rg[14]), "=r"(rg[15]),
                  "=r"(rg[16]), "=r"(rg[17]), "=r"(rg[18]), "=r"(rg[19]),
                  "=r"(rg[20]), "=r"(rg[21]), "=r"(rg[22]), "=r"(rg[23]),
                  "=r"(rg[24]), "=r"(rg[25]), "=r"(rg[26]), "=r"(rg[27]),
                  "=r"(rg[28]), "=r"(rg[29]), "=r"(rg[30]), "=r"(rg[31])
                : "r"(tmem + woff + colhalf * 128 + ch * 32));
            asm volatile("tcgen05.wait::ld.sync.aligned;" ::: "memory");
            int nbase = n0 + colhalf * 128 + ch * 32;
            if (mode == 1) {
                __nv_bfloat16* ph_ = outH + ((size_t)e * CAP + m) * Ntot + nbase;
                __nv_bfloat16* pl_ = outL + ((size_t)e * CAP + m) * Ntot + nbase;
#pragma unroll
                for (int j = 0; j < 32; j += 2) {
                    float v0 = __uint_as_float(rg[j])     + ebias[nbase + j];
                    float v1 = __uint_as_float(rg[j + 1]) + ebias[nbase + j + 1];
                    v0 = 0.5f * v0 * (1.f + erff(v0 * 0.70710678118654752f));
                    v1 = 0.5f * v1 * (1.f + erff(v1 * 0.70710678118654752f));
                    __nv_bfloat16 h0 = __float2bfloat16(v0);
                    __nv_bfloat16 h1 = __float2bfloat16(v1);
                    __nv_bfloat16 l0 = __float2bfloat16(v0 - __bfloat162float(h0));
                    __nv_bfloat16 l1 = __float2bfloat16(v1 - __bfloat162float(h1));
                    *(__nv_bfloat162*)(ph_ + j) = __halves2bfloat162(h0, h1);
                    *(__nv_bfloat162*)(pl_ + j) = __halves2bfloat162(l0, l1);
                }
            } else {
                float* po = outF + ((size_t)e * CAP + m) * Ntot + nbase;
#pragma unroll
                for (int j = 0; j < 32; j += 4) {
                    float4 v;
                    v.x = __uint_as_float(rg[j])     + ebias[nbase + j];
                    v.y = __uint_as_float(rg[j + 1]) + ebias[nbase + j + 1];
                    v.z = __uint_as_float(rg[j + 2]) + ebias[nbase + j + 2];
                    v.w = __uint_as_float(rg[j + 3]) + ebias[nbase + j + 3];
                    *(float4*)(po + j) = v;
                }
            }
        }
    }
    __syncthreads();
    if (wid == 0) {
        asm volatile("tcgen05.relinquish_alloc_permit.cta_group::1.sync.aligned;");
        asm volatile("tcgen05.dealloc.cta_group::1.sync.aligned.b32 %0, 256;" :: "r"(tmem));
    }
#else
    (void)tAh; (void)tAl; (void)tBh; (void)tBl; (void)bias;
    (void)outH; (void)outL; (void)outF; (void)K; (void)Ntot; (void)mode;
#endif
}

// ---------------- 5. deterministic combine ----------------
__global__ void combine_kernel(float* __restrict__ out)
{
    int t = blockIdx.x;
    int i0 = g_topi[t * 2 + 0], i1 = g_topi[t * 2 + 1];
    int p0 = g_pos [t * 2 + 0], p1 = g_pos [t * 2 + 1];
    float gv0 = g_gate[t * 2 + 0], gv1 = g_gate[t * 2 + 1];
    float4 acc = make_float4(0.f, 0.f, 0.f, 0.f);
    int d4 = threadIdx.x;
    if (p0 >= 0) {
        float4 a = ((const float4*)(g_out2 + ((size_t)i0 * CAP + p0) * Dd))[d4];
        acc.x += gv0 * a.x; acc.y += gv0 * a.y; acc.z += gv0 * a.z; acc.w += gv0 * a.w;
    }
    if (p1 >= 0) {
        float4 b = ((const float4*)(g_out2 + ((size_t)i1 * CAP + p1) * Dd))[d4];
        acc.x += gv1 * b.x; acc.y += gv1 * b.y; acc.z += gv1 * b.z; acc.w += gv1 * b.w;
    }
    ((float4*)(out + (size_t)t * Dd))[d4] = acc;
}

// ---------------- host: tensormap encoding via driver entry point ----------------
typedef CUresult (*EncodeFn)(CUtensorMap*, CUtensorMapDataType, cuuint32_t, void*,
                             const cuuint64_t*, const cuuint64_t*, const cuuint32_t*,
                             const cuuint32_t*, CUtensorMapInterleave, CUtensorMapSwizzle,
                             CUtensorMapL2promotion, CUtensorMapFloatOOBfill);

static void encode3d(EncodeFn enc, CUtensorMap* tm, void* ptr,
                     uint64_t kdim, uint64_t rows, uint32_t boxRows)
{
    cuuint64_t dims[3]    = {kdim, rows, (cuuint64_t)Ee};
    cuuint64_t strides[2] = {kdim * 2, (cuuint64_t)rows * kdim * 2};
    cuuint32_t box[3]     = {32, boxRows, 1};   // 32 bf16 = 64B inner box -> SW64
    cuuint32_t estr[3]    = {1, 1, 1};
    enc(tm, CU_TENSOR_MAP_DATA_TYPE_BFLOAT16, 3, ptr, dims, strides, box, estr,
        CU_TENSOR_MAP_INTERLEAVE_NONE, CU_TENSOR_MAP_SWIZZLE_64B,
        CU_TENSOR_MAP_L2_PROMOTION_L2_128B, CU_TENSOR_MAP_FLOAT_OOB_FILL_NONE);
}

// ---------------- launch ----------------
extern "C" void kernel_launch(void* const* d_in, const int* in_sizes, int n_in,
                              void* d_out, int out_size)
{
    const float* x     = (const float*)d_in[0];
    const float* noise = (const float*)d_in[1];
    const float* Wg    = (const float*)d_in[2];
    const float* bg    = (const float*)d_in[3];
    const float* Wn    = (const float*)d_in[4];
    const float* bn    = (const float*)d_in[5];
    const float* W1    = (const float*)d_in[6];
    const float* b1    = (const float*)d_in[7];
    const float* W2    = (const float*)d_in[8];
    const float* b2    = (const float*)d_in[9];
    float* out = (float*)d_out;

    const int GEMM_SMEM = 1024 + 4 * 49152;   // 197632
    cudaFuncSetAttribute(moe_gemm_tma,
                         cudaFuncAttributeMaxDynamicSharedMemorySize, GEMM_SMEM);

    __nv_bfloat16 *xin_h, *xin_l, *w1t_h, *w1t_l, *w2t_h, *w2t_l, *h_h, *h_l;
    float* out2;
    cudaGetSymbolAddress((void**)&xin_h, g_xin_h);
    cudaGetSymbolAddress((void**)&xin_l, g_xin_l);
    cudaGetSymbolAddress((void**)&w1t_h, g_w1t_h);
    cudaGetSymbolAddress((void**)&w1t_l, g_w1t_l);
    cudaGetSymbolAddress((void**)&w2t_h, g_w2t_h);
    cudaGetSymbolAddress((void**)&w2t_l, g_w2t_l);
    cudaGetSymbolAddress((void**)&h_h, g_h_h);
    cudaGetSymbolAddress((void**)&h_l, g_h_l);
    cudaGetSymbolAddress((void**)&out2, g_out2);

    EncodeFn enc = nullptr;
    cudaDriverEntryPointQueryResult qr;
    cudaGetDriverEntryPoint("cuTensorMapEncodeTiled", (void**)&enc,
                            cudaEnableDefault, &qr);

    CUtensorMap t1Ah, t1Al, t1Bh, t1Bl, t2Ah, t2Al, t2Bh, t2Bl;
    // GEMM1: A = xin [E, CAP, D], B = w1t [E, FF, D]
    encode3d(enc, &t1Ah, xin_h, Dd, CAP, 128);
    encode3d(enc, &t1Al, xin_l, Dd, CAP, 128);
    encode3d(enc, &t1Bh, w1t_h, Dd, FFf, 256);
    encode3d(enc, &t1Bl, w1t_l, Dd, FFf, 256);
    // GEMM2: A = h [E, CAP, FF], B = w2t [E, D, FF]
    encode3d(enc, &t2Ah, h_h, FFf, CAP, 128);
    encode3d(enc, &t2Al, h_l, FFf, CAP, 128);
    encode3d(enc, &t2Bh, w2t_h, FFf, Dd, 256);
    encode3d(enc, &t2Bl, w2t_l, FFf, Dd, 256);

    // launches: 1 gating, 2 scan, 3 fused_prep, 4 GEMM1, 5 GEMM2, 6 combine
    gating_kernel<<<F_TOT / 8, 256>>>(x, noise, Wg, bg, Wn, bn);
    scan_kernel<<<Ee, 256>>>();
    fused_prep_kernel<<<65536 + Ee * CAP, 256>>>(W1, W2, x);

    // GEMM1: M=CAP, N=FF, K=D; bias b1; GELU; split-bf16 output
    moe_gemm_tma<<<dim3(FFf / 256, CAP / 128, Ee), 256, GEMM_SMEM>>>(
        t1Ah, t1Al, t1Bh, t1Bl, b1, h_h, h_l, nullptr, Dd, FFf, 1);
    // GEMM2: M=CAP, N=D, K=FF; bias b2; fp32 output
    moe_gemm_tma<<<dim3(Dd / 256, CAP / 128, Ee), 256, GEMM_SMEM>>>(
        t2Ah, t2Al, t2Bh, t2Bl, b2, nullptr, nullptr, out2, FFf, Dd, 0);

    combine_kernel<<<F_TOT, 256>>>(out);
}